// round 1
// baseline (speedup 1.0000x reference)
#include <cuda_runtime.h>
#include <math.h>

#define SEQ 2048
#define EMB 2048
#define NH  16
#define HD  128

// Scratch (allocation-free: __device__ globals)
__device__ float g_q[SEQ * EMB];
__device__ float g_k[SEQ * EMB];
__device__ float g_v[SEQ * EMB];
__device__ float g_ctx[SEQ * EMB];
__device__ float g_scores[(size_t)NH * SEQ * SEQ];   // 256 MB
__device__ float g_invfreq[HD / 2];

// ---------------------------------------------------------------------------
// inv_freq table in fp64 (matches jnp's fp32 pow to ~1-2 ulp after rounding)
// ---------------------------------------------------------------------------
__global__ void init_invfreq_kernel() {
    int j = threadIdx.x;
    if (j < HD / 2) {
        double e = pow(10000.0, -(double)j / (double)(HD / 2));
        g_invfreq[j] = (float)e;
    }
}

// ---------------------------------------------------------------------------
// Tiled SGEMM: C = alpha * A @ op(B)
//   A: [M,K] row-major (lda), B: BT ? [N,K] : [K,N] row-major (ldb)
//   Tiles: BM=BN=128, BK=16; 256 threads; 8x8 per-thread accumulators.
//   Batched over blockIdx.z via element-offset strides.
//   All problem dims here are multiples of the tiles -> no bounds checks.
// ---------------------------------------------------------------------------
template <bool BT>
__global__ __launch_bounds__(256, 2)
void sgemm128(const float* __restrict__ Ab, const float* __restrict__ Bb,
              float* __restrict__ Cb, int K,
              int lda, int ldb, int ldc,
              long aBatch, long bBatch, long cBatch, float alpha)
{
    __shared__ float As[16][128];
    __shared__ float Bs[16][128];

    const float* A = Ab + (long)blockIdx.z * aBatch;
    const float* B = Bb + (long)blockIdx.z * bBatch;
    float*       C = Cb + (long)blockIdx.z * cBatch;

    const int row0 = blockIdx.y * 128;
    const int col0 = blockIdx.x * 128;
    const int tid  = threadIdx.x;
    const int tx   = tid & 15;
    const int ty   = tid >> 4;

    float acc[8][8];
#pragma unroll
    for (int i = 0; i < 8; i++)
#pragma unroll
        for (int j = 0; j < 8; j++) acc[i][j] = 0.f;

    for (int k0 = 0; k0 < K; k0 += 16) {
        // --- A tile: 128 rows x 16 k, store transposed As[k][m] ---
#pragma unroll
        for (int p = 0; p < 2; p++) {
            int i = tid * 4 + p * 1024;
            int r = i >> 4, c = i & 15;
            float4 v = *(const float4*)(A + (long)(row0 + r) * lda + (k0 + c));
            As[c + 0][r] = v.x; As[c + 1][r] = v.y;
            As[c + 2][r] = v.z; As[c + 3][r] = v.w;
        }
        if (BT) {
            // B [N,K]: 128 n-rows x 16 k, store transposed Bs[k][n]
#pragma unroll
            for (int p = 0; p < 2; p++) {
                int i = tid * 4 + p * 1024;
                int r = i >> 4, c = i & 15;
                float4 v = *(const float4*)(B + (long)(col0 + r) * ldb + (k0 + c));
                Bs[c + 0][r] = v.x; Bs[c + 1][r] = v.y;
                Bs[c + 2][r] = v.z; Bs[c + 3][r] = v.w;
            }
        } else {
            // B [K,N]: 16 k-rows x 128 n, direct Bs[k][n]
#pragma unroll
            for (int p = 0; p < 2; p++) {
                int i = tid * 4 + p * 1024;
                int r = i >> 7, c = i & 127;
                float4 v = *(const float4*)(B + (long)(k0 + r) * ldb + (col0 + c));
                *(float4*)&Bs[r][c] = v;
            }
        }
        __syncthreads();

#pragma unroll
        for (int kk = 0; kk < 16; kk++) {
            float a[8], b[8];
            *(float4*)&a[0] = *(const float4*)&As[kk][ty * 8];
            *(float4*)&a[4] = *(const float4*)&As[kk][ty * 8 + 4];
            *(float4*)&b[0] = *(const float4*)&Bs[kk][tx * 8];
            *(float4*)&b[4] = *(const float4*)&Bs[kk][tx * 8 + 4];
#pragma unroll
            for (int i = 0; i < 8; i++)
#pragma unroll
                for (int j = 0; j < 8; j++)
                    acc[i][j] = fmaf(a[i], b[j], acc[i][j]);
        }
        __syncthreads();
    }

#pragma unroll
    for (int i = 0; i < 8; i++) {
        float* cp = C + (long)(row0 + ty * 8 + i) * ldc + col0 + tx * 8;
        float4 o0, o1;
        o0.x = acc[i][0] * alpha; o0.y = acc[i][1] * alpha;
        o0.z = acc[i][2] * alpha; o0.w = acc[i][3] * alpha;
        o1.x = acc[i][4] * alpha; o1.y = acc[i][5] * alpha;
        o1.z = acc[i][6] * alpha; o1.w = acc[i][7] * alpha;
        *(float4*)cp       = o0;
        *(float4*)(cp + 4) = o1;
    }
}

// ---------------------------------------------------------------------------
// In-place RoPE on a [S, H*D] buffer. One thread per (s, h, j) pair, j < D/2.
// ---------------------------------------------------------------------------
__global__ void rope_kernel(float* __restrict__ x) {
    int idx = blockIdx.x * blockDim.x + threadIdx.x;   // SEQ*NH*64 = 2,097,152
    if (idx >= SEQ * NH * (HD / 2)) return;
    int j = idx & 63;
    int h = (idx >> 6) & (NH - 1);
    int s = idx >> 10;

    float inv   = g_invfreq[j];
    float theta = (float)s * inv;
    float c, sn;
    sincosf(theta, &sn, &c);

    long base = (long)s * EMB + h * HD;
    float x1 = x[base + j];
    float x2 = x[base + 64 + j];
    x[base + j]      = x1 * c - x2 * sn;
    x[base + 64 + j] = x2 * c + x1 * sn;
}

// ---------------------------------------------------------------------------
// Row softmax over 2048-wide rows, in place. One block per row, 256 threads.
// ---------------------------------------------------------------------------
__global__ void softmax_kernel(float* __restrict__ sc) {
    float* row = sc + (long)blockIdx.x * SEQ;
    __shared__ float red[256];
    int t = threadIdx.x;

    float v[8];
    float m = -INFINITY;
#pragma unroll
    for (int i = 0; i < 8; i++) {
        v[i] = row[t + i * 256];
        m = fmaxf(m, v[i]);
    }
    red[t] = m; __syncthreads();
    for (int s2 = 128; s2 > 0; s2 >>= 1) {
        if (t < s2) red[t] = fmaxf(red[t], red[t + s2]);
        __syncthreads();
    }
    m = red[0]; __syncthreads();

    float sum = 0.f;
#pragma unroll
    for (int i = 0; i < 8; i++) {
        v[i] = expf(v[i] - m);
        sum += v[i];
    }
    red[t] = sum; __syncthreads();
    for (int s2 = 128; s2 > 0; s2 >>= 1) {
        if (t < s2) red[t] += red[t + s2];
        __syncthreads();
    }
    float inv = 1.f / red[0];
#pragma unroll
    for (int i = 0; i < 8; i++)
        row[t + i * 256] = v[i] * inv;
}

// ---------------------------------------------------------------------------
// Launch
// ---------------------------------------------------------------------------
extern "C" void kernel_launch(void* const* d_in, const int* in_sizes, int n_in,
                              void* d_out, int out_size)
{
    const float* X  = (const float*)d_in[0];
    const float* Wq = (const float*)d_in[1];
    const float* Wk = (const float*)d_in[2];
    const float* Wv = (const float*)d_in[3];
    const float* Wo = (const float*)d_in[4];
    float* out = (float*)d_out;

    float *q, *k, *v, *ctx, *sc;
    cudaGetSymbolAddress((void**)&q,   g_q);
    cudaGetSymbolAddress((void**)&k,   g_k);
    cudaGetSymbolAddress((void**)&v,   g_v);
    cudaGetSymbolAddress((void**)&ctx, g_ctx);
    cudaGetSymbolAddress((void**)&sc,  g_scores);

    const float scale = 0.08838834764831845f;   // 1/sqrt(128)

    init_invfreq_kernel<<<1, 64>>>();

    dim3 blk(256);
    dim3 gProj(EMB / 128, SEQ / 128, 1);        // 16 x 16
    // QKV projections: C = X @ W^T  (NT)
    sgemm128<true><<<gProj, blk>>>(X, Wq, q, EMB, EMB, EMB, EMB, 0, 0, 0, 1.f);
    sgemm128<true><<<gProj, blk>>>(X, Wk, k, EMB, EMB, EMB, EMB, 0, 0, 0, 1.f);
    sgemm128<true><<<gProj, blk>>>(X, Wv, v, EMB, EMB, EMB, EMB, 0, 0, 0, 1.f);

    int ropeN = SEQ * NH * (HD / 2);
    rope_kernel<<<(ropeN + 255) / 256, 256>>>(q);
    rope_kernel<<<(ropeN + 255) / 256, 256>>>(k);

    // scores[h] = scale * Q_h @ K_h^T   (NT, K=128, batched over heads)
    dim3 gScores(SEQ / 128, SEQ / 128, NH);     // 16 x 16 x 16
    sgemm128<true><<<gScores, blk>>>(q, k, sc, HD, EMB, EMB, SEQ,
                                     HD, HD, (long)SEQ * SEQ, scale);

    softmax_kernel<<<NH * SEQ, 256>>>(sc);

    // ctx[h] = P_h @ V_h   (NN, N=128, K=2048, batched over heads)
    dim3 gPV(HD / 128, SEQ / 128, NH);          // 1 x 16 x 16
    sgemm128<false><<<gPV, blk>>>(sc, v, ctx, SEQ, SEQ, EMB, EMB,
                                  (long)SEQ * SEQ, HD, HD, 1.f);

    // out = ctx @ Wo^T   (NT)
    sgemm128<true><<<gProj, blk>>>(ctx, Wo, out, EMB, EMB, EMB, EMB, 0, 0, 0, 1.f);
}

// round 3
// speedup vs baseline: 2.1022x; 2.1022x over previous
#include <cuda_runtime.h>
#include <cuda_bf16.h>
#include <math.h>
#include <stdint.h>

#define SEQ 2048
#define EMB 2048
#define NH  16
#define HD  128

typedef __nv_bfloat16 bf16;

// ---------------- fp32 scratch ----------------
__device__ __align__(256) float g_q[SEQ * EMB];
__device__ __align__(256) float g_k[SEQ * EMB];
__device__ __align__(256) float g_v[SEQ * EMB];
__device__ __align__(256) float g_ctx[SEQ * EMB];
__device__ __align__(256) float g_scores[(size_t)NH * SEQ * SEQ];
__device__ float g_invfreq[HD / 2];

// ---------------- bf16 hi/lo scratch ----------------
__device__ __align__(256) bf16 g_xh[SEQ * EMB],  g_xl[SEQ * EMB];
__device__ __align__(256) bf16 g_wqh[EMB * EMB], g_wql[EMB * EMB];
__device__ __align__(256) bf16 g_wkh[EMB * EMB], g_wkl[EMB * EMB];
__device__ __align__(256) bf16 g_wvh[EMB * EMB], g_wvl[EMB * EMB];
__device__ __align__(256) bf16 g_woh[EMB * EMB], g_wol[EMB * EMB];
__device__ __align__(256) bf16 g_qh[SEQ * EMB],  g_ql[SEQ * EMB];
__device__ __align__(256) bf16 g_kh[SEQ * EMB],  g_kl[SEQ * EMB];
__device__ __align__(256) bf16 g_vth[EMB * SEQ], g_vtl[EMB * SEQ];
__device__ __align__(256) bf16 g_sch[(size_t)NH * SEQ * SEQ];
__device__ __align__(256) bf16 g_scl[(size_t)NH * SEQ * SEQ];
__device__ __align__(256) bf16 g_cxh[SEQ * EMB], g_cxl[SEQ * EMB];

// ---------------------------------------------------------------------------
__global__ void init_invfreq_kernel() {
    int j = threadIdx.x;
    if (j < HD / 2) {
        double e = pow(10000.0, -(double)j / (double)(HD / 2));
        g_invfreq[j] = (float)e;
    }
}

// ---------------------------------------------------------------------------
// fp32 -> (hi, lo) bf16 split, 4 elems/thread
// ---------------------------------------------------------------------------
__global__ void split_kernel(const float* __restrict__ s,
                             bf16* __restrict__ h, bf16* __restrict__ l,
                             int n4) {
    int i = blockIdx.x * blockDim.x + threadIdx.x;
    if (i >= n4) return;
    float4 v = ((const float4*)s)[i];
    bf16 h0 = __float2bfloat16_rn(v.x);
    bf16 h1 = __float2bfloat16_rn(v.y);
    bf16 h2 = __float2bfloat16_rn(v.z);
    bf16 h3 = __float2bfloat16_rn(v.w);
    bf16 l0 = __float2bfloat16_rn(v.x - __bfloat162float(h0));
    bf16 l1 = __float2bfloat16_rn(v.y - __bfloat162float(h1));
    bf16 l2 = __float2bfloat16_rn(v.z - __bfloat162float(h2));
    bf16 l3 = __float2bfloat16_rn(v.w - __bfloat162float(h3));
    __nv_bfloat162 ph0 = __halves2bfloat162(h0, h1);
    __nv_bfloat162 ph1 = __halves2bfloat162(h2, h3);
    __nv_bfloat162 pl0 = __halves2bfloat162(l0, l1);
    __nv_bfloat162 pl1 = __halves2bfloat162(l2, l3);
    uint2 uh, ul;
    uh.x = *(unsigned*)&ph0; uh.y = *(unsigned*)&ph1;
    ul.x = *(unsigned*)&pl0; ul.y = *(unsigned*)&pl1;
    ((uint2*)h)[i] = uh;
    ((uint2*)l)[i] = ul;
}

// ---------------------------------------------------------------------------
// V [S][E] fp32 -> Vt hi/lo bf16 [E][S]  (so PV becomes an NT GEMM)
// ---------------------------------------------------------------------------
__global__ void vtrans_split_kernel(const float* __restrict__ v,
                                    bf16* __restrict__ th, bf16* __restrict__ tl) {
    __shared__ float t[32][33];
    int e0 = blockIdx.x * 32, s0 = blockIdx.y * 32;
    int x = threadIdx.x, y = threadIdx.y;   // 32 x 8
#pragma unroll
    for (int j = 0; j < 32; j += 8)
        t[y + j][x] = v[(long)(s0 + y + j) * EMB + e0 + x];
    __syncthreads();
#pragma unroll
    for (int j = 0; j < 32; j += 8) {
        float val = t[x][y + j];
        bf16 hi = __float2bfloat16_rn(val);
        bf16 lo = __float2bfloat16_rn(val - __bfloat162float(hi));
        long o = (long)(e0 + y + j) * SEQ + s0 + x;
        th[o] = hi;
        tl[o] = lo;
    }
}

// ---------------------------------------------------------------------------
// bf16x3 NT GEMM:  C[M][N] = alpha * sum_k A[m][k] * B[n][k]
//   A ~ (Ah + Al), B ~ (Bh + Bl); 3-term product (drop Al*Bl).
//   CTA tile 128x128x32, 8 warps (warp tile 64x32), cp.async double buffer.
// ---------------------------------------------------------------------------
#define SK  40                  // padded smem k-stride (bf16 elems)
#define TSZ (128 * SK)          // elems per smem tile

__device__ __forceinline__ void mma_bf16(float* c, const unsigned* a, const unsigned* b) {
    asm volatile(
        "mma.sync.aligned.m16n8k16.row.col.f32.bf16.bf16.f32 "
        "{%0,%1,%2,%3}, {%4,%5,%6,%7}, {%8,%9}, {%0,%1,%2,%3};"
        : "+f"(c[0]), "+f"(c[1]), "+f"(c[2]), "+f"(c[3])
        : "r"(a[0]), "r"(a[1]), "r"(a[2]), "r"(a[3]), "r"(b[0]), "r"(b[1]));
}

__device__ __forceinline__ void cp16(unsigned s, const void* g) {
    asm volatile("cp.async.cg.shared.global [%0], [%1], 16;" :: "r"(s), "l"(g));
}

__global__ __launch_bounds__(256, 1)
void gemm_bf16x3(const bf16* __restrict__ Ah, const bf16* __restrict__ Al,
                 const bf16* __restrict__ Bh, const bf16* __restrict__ Bl,
                 float* __restrict__ C, int K,
                 int lda, int ldb, int ldc,
                 long aB, long bB, long cB, float alpha)
{
    extern __shared__ bf16 sm[];

    Ah += (long)blockIdx.z * aB; Al += (long)blockIdx.z * aB;
    Bh += (long)blockIdx.z * bB; Bl += (long)blockIdx.z * bB;
    C  += (long)blockIdx.z * cB;

    const int row0 = blockIdx.y * 128;
    const int col0 = blockIdx.x * 128;
    const int tid  = threadIdx.x;
    const int lane = tid & 31;
    const int wid  = tid >> 5;
    const int m0 = (wid & 1) * 64;
    const int n0 = (wid >> 1) * 32;

    // per-thread cp.async coords: rows tid/4 and tid/4+64, 16B chunk (tid&3)*8
    const int lr = tid >> 2;
    const int lc = (tid & 3) * 8;
    const bf16* gp0[4];
    const bf16* gp1[4];
    gp0[0] = Ah + (long)(row0 + lr) * lda + lc;  gp1[0] = gp0[0] + (long)64 * lda;
    gp0[1] = Al + (long)(row0 + lr) * lda + lc;  gp1[1] = gp0[1] + (long)64 * lda;
    gp0[2] = Bh + (long)(col0 + lr) * ldb + lc;  gp1[2] = gp0[2] + (long)64 * ldb;
    gp0[3] = Bl + (long)(col0 + lr) * ldb + lc;  gp1[3] = gp0[3] + (long)64 * ldb;

    const unsigned sb = (unsigned)__cvta_generic_to_shared(sm);
    const unsigned so0 = (lr * SK + lc) * 2;
    const unsigned so1 = ((lr + 64) * SK + lc) * 2;

    float acc[4][4][4];
#pragma unroll
    for (int a = 0; a < 4; a++)
#pragma unroll
        for (int b = 0; b < 4; b++)
#pragma unroll
            for (int c = 0; c < 4; c++) acc[a][b][c] = 0.f;

    const int NIT = K / 32;

#define ISSUE(st, k0)                                                        \
    {                                                                        \
        unsigned base = sb + (unsigned)(st) * (4u * TSZ * 2u);               \
        _Pragma("unroll")                                                    \
        for (int t = 0; t < 4; t++) {                                        \
            cp16(base + (unsigned)t * (TSZ * 2u) + so0, gp0[t] + (k0));      \
            cp16(base + (unsigned)t * (TSZ * 2u) + so1, gp1[t] + (k0));      \
        }                                                                    \
    }

    ISSUE(0, 0);
    asm volatile("cp.async.commit_group;");

    for (int it = 0; it < NIT; it++) {
        if (it + 1 < NIT) {
            ISSUE((it + 1) & 1, (it + 1) * 32);
            asm volatile("cp.async.commit_group;");
            asm volatile("cp.async.wait_group 1;");
        } else {
            asm volatile("cp.async.wait_group 0;");
        }
        __syncthreads();

        const bf16* sAh = sm + (it & 1) * 4 * TSZ;
        const bf16* sAl = sAh + TSZ;
        const bf16* sBh = sAh + 2 * TSZ;
        const bf16* sBl = sAh + 3 * TSZ;

#pragma unroll
        for (int ks = 0; ks < 2; ks++) {
            const int kc = ks * 16 + (lane & 3) * 2;
            const int ra = m0 + (lane >> 2);
            const int rb = n0 + (lane >> 2);

            unsigned ah[4][4], al[4][4];
#pragma unroll
            for (int mi = 0; mi < 4; mi++) {
                int r = ra + mi * 16;
                ah[mi][0] = *(const unsigned*)(sAh + r * SK + kc);
                ah[mi][1] = *(const unsigned*)(sAh + (r + 8) * SK + kc);
                ah[mi][2] = *(const unsigned*)(sAh + r * SK + kc + 8);
                ah[mi][3] = *(const unsigned*)(sAh + (r + 8) * SK + kc + 8);
                al[mi][0] = *(const unsigned*)(sAl + r * SK + kc);
                al[mi][1] = *(const unsigned*)(sAl + (r + 8) * SK + kc);
                al[mi][2] = *(const unsigned*)(sAl + r * SK + kc + 8);
                al[mi][3] = *(const unsigned*)(sAl + (r + 8) * SK + kc + 8);
            }
            unsigned bh[4][2], bl[4][2];
#pragma unroll
            for (int ni = 0; ni < 4; ni++) {
                int r = rb + ni * 8;
                bh[ni][0] = *(const unsigned*)(sBh + r * SK + kc);
                bh[ni][1] = *(const unsigned*)(sBh + r * SK + kc + 8);
                bl[ni][0] = *(const unsigned*)(sBl + r * SK + kc);
                bl[ni][1] = *(const unsigned*)(sBl + r * SK + kc + 8);
            }
#pragma unroll
            for (int mi = 0; mi < 4; mi++)
#pragma unroll
                for (int ni = 0; ni < 4; ni++) {
                    mma_bf16(acc[mi][ni], ah[mi], bh[ni]);
                    mma_bf16(acc[mi][ni], ah[mi], bl[ni]);
                    mma_bf16(acc[mi][ni], al[mi], bh[ni]);
                }
        }
        __syncthreads();
    }

    // epilogue
#pragma unroll
    for (int mi = 0; mi < 4; mi++) {
#pragma unroll
        for (int ni = 0; ni < 4; ni++) {
            int r = row0 + m0 + mi * 16 + (lane >> 2);
            int c = col0 + n0 + ni * 8 + (lane & 3) * 2;
            float2 v0 = make_float2(acc[mi][ni][0] * alpha, acc[mi][ni][1] * alpha);
            float2 v1 = make_float2(acc[mi][ni][2] * alpha, acc[mi][ni][3] * alpha);
            *(float2*)(C + (long)r * ldc + c) = v0;
            *(float2*)(C + (long)(r + 8) * ldc + c) = v1;
        }
    }
}

// ---------------------------------------------------------------------------
// In-place RoPE on [S, H*D] fp32
// ---------------------------------------------------------------------------
__global__ void rope_kernel(float* __restrict__ x) {
    int idx = blockIdx.x * blockDim.x + threadIdx.x;
    if (idx >= SEQ * NH * (HD / 2)) return;
    int j = idx & 63;
    int h = (idx >> 6) & (NH - 1);
    int s = idx >> 10;

    float inv   = g_invfreq[j];
    float theta = (float)s * inv;
    float c, sn;
    sincosf(theta, &sn, &c);

    long base = (long)s * EMB + h * HD;
    float x1 = x[base + j];
    float x2 = x[base + 64 + j];
    x[base + j]      = x1 * c - x2 * sn;
    x[base + 64 + j] = x2 * c + x1 * sn;
}

// ---------------------------------------------------------------------------
// Row softmax over 2048-wide rows; outputs bf16 hi/lo directly (fused split).
// fp32 probs are never written back.
// ---------------------------------------------------------------------------
__global__ void softmax_split_kernel(const float* __restrict__ sc,
                                     bf16* __restrict__ ph,
                                     bf16* __restrict__ pl) {
    const float* row = sc + (long)blockIdx.x * SEQ;
    bf16* rh = ph + (long)blockIdx.x * SEQ;
    bf16* rl = pl + (long)blockIdx.x * SEQ;
    __shared__ float red[256];
    int t = threadIdx.x;

    float v[8];
    float m = -INFINITY;
#pragma unroll
    for (int i = 0; i < 8; i++) {
        v[i] = row[t + i * 256];
        m = fmaxf(m, v[i]);
    }
    red[t] = m; __syncthreads();
    for (int s2 = 128; s2 > 0; s2 >>= 1) {
        if (t < s2) red[t] = fmaxf(red[t], red[t + s2]);
        __syncthreads();
    }
    m = red[0]; __syncthreads();

    float sum = 0.f;
#pragma unroll
    for (int i = 0; i < 8; i++) {
        v[i] = expf(v[i] - m);
        sum += v[i];
    }
    red[t] = sum; __syncthreads();
    for (int s2 = 128; s2 > 0; s2 >>= 1) {
        if (t < s2) red[t] += red[t + s2];
        __syncthreads();
    }
    float inv = 1.f / red[0];
#pragma unroll
    for (int i = 0; i < 8; i++) {
        float p = v[i] * inv;
        bf16 hi = __float2bfloat16_rn(p);
        bf16 lo = __float2bfloat16_rn(p - __bfloat162float(hi));
        rh[t + i * 256] = hi;
        rl[t + i * 256] = lo;
    }
}

// ---------------------------------------------------------------------------
extern "C" void kernel_launch(void* const* d_in, const int* in_sizes, int n_in,
                              void* d_out, int out_size)
{
    const float* X  = (const float*)d_in[0];
    const float* Wq = (const float*)d_in[1];
    const float* Wk = (const float*)d_in[2];
    const float* Wv = (const float*)d_in[3];
    const float* Wo = (const float*)d_in[4];
    float* out = (float*)d_out;

    float *q, *k, *v, *ctx, *sc;
    cudaGetSymbolAddress((void**)&q,   g_q);
    cudaGetSymbolAddress((void**)&k,   g_k);
    cudaGetSymbolAddress((void**)&v,   g_v);
    cudaGetSymbolAddress((void**)&ctx, g_ctx);
    cudaGetSymbolAddress((void**)&sc,  g_scores);

    bf16 *xh, *xl, *wqh, *wql, *wkh, *wkl, *wvh, *wvl, *woh, *wol;
    bf16 *qh, *ql, *kh, *kl, *vth, *vtl, *sch, *scl, *cxh, *cxl;
    cudaGetSymbolAddress((void**)&xh,  g_xh);   cudaGetSymbolAddress((void**)&xl,  g_xl);
    cudaGetSymbolAddress((void**)&wqh, g_wqh);  cudaGetSymbolAddress((void**)&wql, g_wql);
    cudaGetSymbolAddress((void**)&wkh, g_wkh);  cudaGetSymbolAddress((void**)&wkl, g_wkl);
    cudaGetSymbolAddress((void**)&wvh, g_wvh);  cudaGetSymbolAddress((void**)&wvl, g_wvl);
    cudaGetSymbolAddress((void**)&woh, g_woh);  cudaGetSymbolAddress((void**)&wol, g_wol);
    cudaGetSymbolAddress((void**)&qh,  g_qh);   cudaGetSymbolAddress((void**)&ql,  g_ql);
    cudaGetSymbolAddress((void**)&kh,  g_kh);   cudaGetSymbolAddress((void**)&kl,  g_kl);
    cudaGetSymbolAddress((void**)&vth, g_vth);  cudaGetSymbolAddress((void**)&vtl, g_vtl);
    cudaGetSymbolAddress((void**)&sch, g_sch);  cudaGetSymbolAddress((void**)&scl, g_scl);
    cudaGetSymbolAddress((void**)&cxh, g_cxh);  cudaGetSymbolAddress((void**)&cxl, g_cxl);

    const int SMEM = 2 * 4 * TSZ * 2;   // 81920 B
    cudaFuncSetAttribute(gemm_bf16x3, cudaFuncAttributeMaxDynamicSharedMemorySize, SMEM);

    const float scale = 0.08838834764831845f;   // 1/sqrt(128)

    init_invfreq_kernel<<<1, 64>>>();

    // splits of inputs
    int nEl = SEQ * EMB, n4 = nEl / 4;
    split_kernel<<<n4 / 256, 256>>>(X,  xh,  xl,  n4);
    split_kernel<<<n4 / 256, 256>>>(Wq, wqh, wql, n4);
    split_kernel<<<n4 / 256, 256>>>(Wk, wkh, wkl, n4);
    split_kernel<<<n4 / 256, 256>>>(Wv, wvh, wvl, n4);
    split_kernel<<<n4 / 256, 256>>>(Wo, woh, wol, n4);

    dim3 blk(256);
    dim3 gProj(EMB / 128, SEQ / 128, 1);
    gemm_bf16x3<<<gProj, blk, SMEM>>>(xh, xl, wqh, wql, q, EMB, EMB, EMB, EMB, 0, 0, 0, 1.f);
    gemm_bf16x3<<<gProj, blk, SMEM>>>(xh, xl, wkh, wkl, k, EMB, EMB, EMB, EMB, 0, 0, 0, 1.f);
    gemm_bf16x3<<<gProj, blk, SMEM>>>(xh, xl, wvh, wvl, v, EMB, EMB, EMB, EMB, 0, 0, 0, 1.f);

    int ropeN = SEQ * NH * (HD / 2);
    rope_kernel<<<(ropeN + 255) / 256, 256>>>(q);
    rope_kernel<<<(ropeN + 255) / 256, 256>>>(k);

    split_kernel<<<n4 / 256, 256>>>(q, qh, ql, n4);
    split_kernel<<<n4 / 256, 256>>>(k, kh, kl, n4);
    vtrans_split_kernel<<<dim3(EMB / 32, SEQ / 32), dim3(32, 8)>>>(v, vth, vtl);

    // scores[h] = scale * Q_h @ K_h^T   (K=128, per-head k-offset = h*128)
    dim3 gScores(SEQ / 128, SEQ / 128, NH);
    gemm_bf16x3<<<gScores, blk, SMEM>>>(qh, ql, kh, kl, sc, HD, EMB, EMB, SEQ,
                                        HD, HD, (long)SEQ * SEQ, scale);

    // fused softmax + bf16 hi/lo split
    softmax_split_kernel<<<NH * SEQ, 256>>>(sc, sch, scl);

    // ctx[h] = P_h @ Vt_h^T   (NT via pre-transposed V)
    dim3 gPV(1, SEQ / 128, NH);
    gemm_bf16x3<<<gPV, blk, SMEM>>>(sch, scl, vth, vtl, ctx, SEQ, SEQ, SEQ, EMB,
                                    (long)SEQ * SEQ, (long)HD * SEQ, HD, 1.f);

    // out = ctx @ Wo^T
    split_kernel<<<n4 / 256, 256>>>(ctx, cxh, cxl, n4);
    gemm_bf16x3<<<gProj, blk, SMEM>>>(cxh, cxl, woh, wol, out, EMB, EMB, EMB, EMB, 0, 0, 0, 1.f);
}